// round 6
// baseline (speedup 1.0000x reference)
#include <cuda_runtime.h>
#include <math.h>

#define Bn 32
#define Nn 1024
#define Fn 128
#define Dn 128

// dk = (D^-0.5)/N = 1/(sqrt(128)*1024)
#define DKC 8.6316745750311e-05f

typedef unsigned long long ull;

// ---------------- scratch (device globals) ----------------
__device__ float g_M[Fn * Fn];
__device__ float g_Apart[Bn][16][Fn];
__device__ float g_wcomb[Bn][Fn];
__device__ float g_ccomb[Bn];
__device__ float g_n2part[Bn][16];
__device__ float g_invn[Bn];
__device__ float g_Zpart[Bn][16];
__device__ float g_upart[Bn][16][Fn];
__device__ float g_invZ[Bn];
__device__ int   g_cnt1[Bn], g_cnt2[Bn], g_cnt3[Bn], g_cnt4[Bn];
__device__ int   g_flagW[Bn], g_flagN[Bn], g_flagZ[Bn];

// ---------------- f32x2 helpers ----------------
__device__ __forceinline__ void ffma2(ull& d, ull a, ull b) {
    asm("fma.rn.f32x2 %0, %1, %2, %0;" : "+l"(d) : "l"(a), "l"(b));
}
__device__ __forceinline__ ull pk2(float lo, float hi) {
    ull r; asm("mov.b64 %0, {%1,%2};" : "=l"(r) : "f"(lo), "f"(hi)); return r;
}
__device__ __forceinline__ void upk2(ull v, float& lo, float& hi) {
    asm("mov.b64 {%0,%1}, %2;" : "=f"(lo), "=f"(hi) : "l"(v));
}
__device__ __forceinline__ void waitflag(int* f, int t) {
    if (t == 0) { while (atomicAdd(f, 0) == 0) __nanosleep(64); }
    __syncthreads();
    __threadfence();
}

// ============ k0: M = Wq Wk^T (two rows per block) ============
__global__ void __launch_bounds__(256) k0(const float* __restrict__ Wq,
                                          const float* __restrict__ Wk) {
    __shared__ float srow[256];
    int blk = blockIdx.x, t = threadIdx.x;
    srow[t] = Wq[blk * 256 + t];
    __syncthreads();
    int row = t >> 7, c = t & 127;
    const float* sr = srow + row * 128;
    const float4* wk4 = reinterpret_cast<const float4*>(Wk + c * Fn);
    float a0 = 0.f, a1 = 0.f, a2 = 0.f, a3 = 0.f;
    #pragma unroll
    for (int q = 0; q < 32; q += 4) {
        float4 v0 = wk4[q + 0], v1 = wk4[q + 1], v2 = wk4[q + 2], v3 = wk4[q + 3];
        a0 = fmaf(sr[4*q + 0], v0.x, a0); a0 = fmaf(sr[4*q + 1], v0.y, a0);
        a0 = fmaf(sr[4*q + 2], v0.z, a0); a0 = fmaf(sr[4*q + 3], v0.w, a0);
        a1 = fmaf(sr[4*q + 4], v1.x, a1); a1 = fmaf(sr[4*q + 5], v1.y, a1);
        a1 = fmaf(sr[4*q + 6], v1.z, a1); a1 = fmaf(sr[4*q + 7], v1.w, a1);
        a2 = fmaf(sr[4*q + 8], v2.x, a2); a2 = fmaf(sr[4*q + 9], v2.y, a2);
        a2 = fmaf(sr[4*q +10], v2.z, a2); a2 = fmaf(sr[4*q +11], v2.w, a2);
        a3 = fmaf(sr[4*q +12], v3.x, a3); a3 = fmaf(sr[4*q +13], v3.y, a3);
        a3 = fmaf(sr[4*q +14], v3.z, a3); a3 = fmaf(sr[4*q +15], v3.w, a3);
    }
    g_M[(2 * blk + row) * Fn + c] = (a0 + a1) + (a2 + a3);
}

// ============ k1: fused everything-else ============
#define STM 129
#define STX 66
#define K1_SMEM ((Fn * STM + Fn * STX) * 4)

__global__ void __launch_bounds__(256, 2) k1(const float* __restrict__ aq,
                                             const float* __restrict__ mask,
                                             const float* __restrict__ Wq,
                                             const float* __restrict__ Wk,
                                             const float* __restrict__ bq,
                                             const float* __restrict__ bk,
                                             const float* __restrict__ Wv,
                                             const float* __restrict__ bv,
                                             float* __restrict__ attn_out,
                                             float* __restrict__ ctx_out) {
    extern __shared__ float sm[];
    float* sM  = sm;                     // [128][129]  (dead after P2 main-loop use)
    float* sXT = sM + Fn * STM;          // [128 f][66] -> sXT[f*STX + atom]
    __shared__ float sWc[128], sA[128], sT[128], sbq[128];
    __shared__ float sMask[64], aggS[64], sE[64];
    __shared__ float sTmp[256];
    __shared__ float sred[8];
    __shared__ int isL1, isL2, isL3;

    const int b = blockIdx.y;
    const int bx = blockIdx.x;
    const int atom0 = bx * 64;
    const int t = threadIdx.x;
    const int warp = t >> 5, lane = t & 31;
    const int r0 = warp * 8;

    // ---------- P0: load M + tile, colsum partial, last block -> wcomb ----------
    for (int idx = t; idx < Fn * Fn; idx += 256)
        sM[(idx >> 7) * STM + (idx & 127)] = g_M[idx];
    const float* aqb = aq + ((size_t)(b * Nn + atom0)) * Fn;
    for (int idx = t; idx < 64 * Fn; idx += 256)
        sXT[(idx & 127) * STX + (idx >> 7)] = aqb[idx];
    if (t < 64) sMask[t] = mask[b * Nn + atom0 + t];
    __syncthreads();

    {   // colsum from SMEM tile
        int f = t & 127, h = (t >> 7) * 32;
        const float* xp = &sXT[f * STX + h];
        float a0 = 0.f, a1 = 0.f, a2 = 0.f, a3 = 0.f;
        #pragma unroll
        for (int a = 0; a < 32; a += 4) {
            a0 += xp[a + 0]; a1 += xp[a + 1]; a2 += xp[a + 2]; a3 += xp[a + 3];
        }
        sTmp[t] = (a0 + a1) + (a2 + a3);
    }
    __syncthreads();
    if (t < 128) g_Apart[b][bx][t] = sTmp[t] + sTmp[t + 128];
    __threadfence();
    __syncthreads();
    if (t == 0) isL1 = (atomicAdd(&g_cnt1[b], 1) == 15);
    __syncthreads();

    if (isL1) {
        if (t < 128) {
            float s = 0.f;
            #pragma unroll
            for (int c = 0; c < 16; c++) s += __ldcg(&g_Apart[b][c][t]);
            sA[t] = s;
            sbq[t] = bq[t];
        }
        __syncthreads();
        if (t < 128) {
            float s0 = 0.f, s1 = 0.f, s2 = 0.f, s3 = 0.f;
            #pragma unroll 8
            for (int f = 0; f < Fn; f += 4) {
                s0 = fmaf(Wk[(f + 0) * Fn + t], sA[f + 0], s0);
                s1 = fmaf(Wk[(f + 1) * Fn + t], sA[f + 1], s1);
                s2 = fmaf(Wk[(f + 2) * Fn + t], sA[f + 2], s2);
                s3 = fmaf(Wk[(f + 3) * Fn + t], sA[f + 3], s3);
            }
            sT[t] = (s0 + s1) + (s2 + s3) + 1023.0f * bk[t];  // S - bk
        }
        __syncthreads();
        float cc = 0.f;
        if (t < 128) {
            const float4* wq4 = reinterpret_cast<const float4*>(Wq + t * Fn);
            const float4* wk4 = reinterpret_cast<const float4*>(Wk + t * Fn);
            float w0 = 0.f, w1 = 0.f, w2 = 0.f, w3 = 0.f;
            #pragma unroll 8
            for (int q = 0; q < 32; q += 2) {
                float4 a = wq4[q], b4 = wk4[q], c4 = wq4[q + 1], d4 = wk4[q + 1];
                int d0 = 4 * q, d1 = 4 * q + 4;
                w0 = fmaf(a.x, sT[d0 + 0], w0);  w1 = fmaf(-b4.x, sbq[d0 + 0], w1);
                w0 = fmaf(a.y, sT[d0 + 1], w0);  w1 = fmaf(-b4.y, sbq[d0 + 1], w1);
                w0 = fmaf(a.z, sT[d0 + 2], w0);  w1 = fmaf(-b4.z, sbq[d0 + 2], w1);
                w0 = fmaf(a.w, sT[d0 + 3], w0);  w1 = fmaf(-b4.w, sbq[d0 + 3], w1);
                w2 = fmaf(c4.x, sT[d1 + 0], w2); w3 = fmaf(-d4.x, sbq[d1 + 0], w3);
                w2 = fmaf(c4.y, sT[d1 + 1], w2); w3 = fmaf(-d4.y, sbq[d1 + 1], w3);
                w2 = fmaf(c4.z, sT[d1 + 2], w2); w3 = fmaf(-d4.z, sbq[d1 + 2], w3);
                w2 = fmaf(c4.w, sT[d1 + 3], w2); w3 = fmaf(-d4.w, sbq[d1 + 3], w3);
            }
            g_wcomb[b][t] = (w0 + w1) + (w2 + w3);
            cc = sbq[t] * sT[t];
        }
        #pragma unroll
        for (int off = 16; off > 0; off >>= 1)
            cc += __shfl_xor_sync(0xffffffffu, cc, off);
        if (lane == 0 && warp < 4) sred[warp] = cc;
        __syncthreads();
        if (t == 0) {
            g_ccomb[b] = sred[0] + sred[1] + sred[2] + sred[3];
            __threadfence();
            atomicExch(&g_flagW[b], 1);
        }
    }

    // ---------- P1: main FFMA2 loop (no cross-block deps) ----------
    ull acc[4][4];
    #pragma unroll
    for (int k = 0; k < 4; k++)
        #pragma unroll
        for (int a2 = 0; a2 < 4; a2++) acc[k][a2] = 0ull;

    #pragma unroll 4
    for (int g = 0; g < Fn; g++) {
        const float* xp = &sXT[g * STX + r0];
        ull x0 = *reinterpret_cast<const ull*>(xp + 0);
        ull x1 = *reinterpret_cast<const ull*>(xp + 2);
        ull x2 = *reinterpret_cast<const ull*>(xp + 4);
        ull x3 = *reinterpret_cast<const ull*>(xp + 6);
        #pragma unroll
        for (int k = 0; k < 4; k++) {
            float m = sM[(lane + 32 * k) * STM + g];
            ull mm = pk2(m, m);
            ffma2(acc[k][0], mm, x0);
            ffma2(acc[k][1], mm, x1);
            ffma2(acc[k][2], mm, x2);
            ffma2(acc[k][3], mm, x3);
        }
    }

    // ---------- P2: wait wcomb, compute agg, n2 partial ----------
    waitflag(&g_flagW[b], t);
    if (t < 128) sWc[t] = __ldcg(&g_wcomb[b][t]);
    __syncthreads();
    const float ccomb = __ldcg(&g_ccomb[b]);

    float wc[4];
    #pragma unroll
    for (int k = 0; k < 4; k++) wc[k] = sWc[lane + 32 * k];

    float n2local = 0.f;
    #pragma unroll
    for (int a2 = 0; a2 < 4; a2++) {
        float ylo[4], yhi[4];
        #pragma unroll
        for (int k = 0; k < 4; k++) upk2(acc[k][a2], ylo[k], yhi[k]);
        #pragma unroll
        for (int half = 0; half < 2; half++) {
            int a = 2 * a2 + half;
            float p1 = 0.f, p2 = 0.f;
            #pragma unroll
            for (int k = 0; k < 4; k++) {
                float xf = sXT[(lane + 32 * k) * STX + r0 + a];
                p1 = fmaf(xf, half ? yhi[k] : ylo[k], p1);
                p2 = fmaf(xf, wc[k], p2);
            }
            #pragma unroll
            for (int off = 16; off > 0; off >>= 1) {
                p1 += __shfl_xor_sync(0xffffffffu, p1, off);
                p2 += __shfl_xor_sync(0xffffffffu, p2, off);
            }
            if (lane == 0) {
                float mv = sMask[r0 + a];
                float aggv = mv * DKC * (p2 + ccomb - p1);
                aggS[r0 + a] = aggv;
                n2local = fmaf(aggv, aggv, n2local);
            }
        }
    }
    if (lane == 0) sred[warp] = n2local;
    __threadfence_block();
    __syncthreads();
    if (t == 0) {
        float s = 0.f;
        #pragma unroll
        for (int w = 0; w < 8; w++) s += sred[w];
        g_n2part[b][bx] = s;
        __threadfence();
        isL2 = (atomicAdd(&g_cnt2[b], 1) == 15);
        if (isL2) {
            float n2 = 0.f;
            #pragma unroll
            for (int c = 0; c < 16; c++) n2 += __ldcg(&g_n2part[b][c]);
            g_invn[b] = rsqrtf(n2);
            __threadfence();
            atomicExch(&g_flagN[b], 1);
        }
    }

    // ---------- P3: wait invn, exp, Z partial, weighted colsum partial ----------
    waitflag(&g_flagN[b], t);
    const float invn = __ldcg(&g_invn[b]);
    if (t < 64) {
        float e = (sMask[t] != 0.f) ? __expf(aggS[t] * invn) : 0.f;
        sE[t] = e;
    }
    __syncthreads();
    if (t < 32) {
        float z = sE[t] + sE[t + 32];
        #pragma unroll
        for (int off = 16; off > 0; off >>= 1) z += __shfl_xor_sync(0xffffffffu, z, off);
        if (t == 0) g_Zpart[b][bx] = z;
    }
    {   // u'[f] = sum_a e_a * x_a[f]
        int f = t & 127, h = (t >> 7) * 32;
        const float* xp = &sXT[f * STX + h];
        const float* ep = &sE[h];
        float a0 = 0.f, a1 = 0.f, a2 = 0.f, a3 = 0.f;
        #pragma unroll
        for (int a = 0; a < 32; a += 4) {
            a0 = fmaf(ep[a + 0], xp[a + 0], a0);
            a1 = fmaf(ep[a + 1], xp[a + 1], a1);
            a2 = fmaf(ep[a + 2], xp[a + 2], a2);
            a3 = fmaf(ep[a + 3], xp[a + 3], a3);
        }
        sTmp[t] = (a0 + a1) + (a2 + a3);
    }
    __syncthreads();
    if (t < 128) g_upart[b][bx][t] = sTmp[t] + sTmp[t + 128];
    __threadfence();
    __syncthreads();
    if (t == 0) {
        isL3 = (atomicAdd(&g_cnt3[b], 1) == 15);
        if (isL3) {
            float Z = 0.f;
            #pragma unroll
            for (int c = 0; c < 16; c++) Z += __ldcg(&g_Zpart[b][c]);
            g_invZ[b] = 1.0f / Z;
            __threadfence();
            atomicExch(&g_flagZ[b], 1);
        }
    }

    // ---------- P4: wait Z, write attn, last block computes context ----------
    waitflag(&g_flagZ[b], t);
    const float invZ = __ldcg(&g_invZ[b]);
    if (attn_out && t < 64)
        attn_out[b * Nn + atom0 + t] = sE[t] * invZ;
    __syncthreads();

    if (isL3) {
        float* sU = sTmp;       // [0..127] reduced u vector
        float* spart = sM;      // separate scratch: extern SMEM region is dead here
        if (t < 128) {
            float s = 0.f;
            #pragma unroll
            for (int c = 0; c < 16; c++) s += __ldcg(&g_upart[b][c][t]);
            sU[t] = s;
        }
        __syncthreads();
        if (ctx_out) {
            int g = t >> 7, d = t & 127;
            int f0 = g * 64;
            float c0 = 0.f, c1 = 0.f, c2 = 0.f, c3 = 0.f;
            #pragma unroll 4
            for (int f = f0; f < f0 + 64; f += 4) {
                c0 = fmaf(Wv[(f + 0) * Fn + d], sU[f + 0], c0);
                c1 = fmaf(Wv[(f + 1) * Fn + d], sU[f + 1], c1);
                c2 = fmaf(Wv[(f + 2) * Fn + d], sU[f + 2], c2);
                c3 = fmaf(Wv[(f + 3) * Fn + d], sU[f + 3], c3);
            }
            spart[t] = (c0 + c1) + (c2 + c3);     // no aliasing with sU now
            __syncthreads();
            if (t < 128)
                ctx_out[b * Dn + t] = (spart[t] + spart[t + 128]) * invZ + bv[t];
        }
    }

    // ---------- P5: arrival + reset for graph replay ----------
    __threadfence();
    __syncthreads();
    if (t == 0) {
        int r = atomicAdd(&g_cnt4[b], 1);
        if (r == 15) {
            g_cnt1[b] = 0; g_cnt2[b] = 0; g_cnt3[b] = 0; g_cnt4[b] = 0;
            g_flagW[b] = 0; g_flagN[b] = 0; g_flagZ[b] = 0;
        }
    }
}

// ---------------- host launch ----------------
extern "C" void kernel_launch(void* const* d_in, const int* in_sizes, int n_in,
                              void* d_out, int out_size) {
    const float* aq   = (const float*)d_in[0];
    const float* mask = (const float*)d_in[1];
    const float* Wq   = (const float*)d_in[2];
    const float* bq   = (const float*)d_in[3];
    const float* Wk   = (const float*)d_in[4];
    const float* bk   = (const float*)d_in[5];
    const float* Wv   = (const float*)d_in[6];
    const float* bv   = (const float*)d_in[7];

    float* out = (float*)d_out;
    float* attn_out = nullptr;
    float* ctx_out = nullptr;
    if (out_size >= Bn * Nn + Bn * Dn) { attn_out = out; ctx_out = out + Bn * Nn; }
    else if (out_size == Bn * Nn)      { attn_out = out; }
    else                               { ctx_out = out; }

    cudaFuncSetAttribute(k1, cudaFuncAttributeMaxDynamicSharedMemorySize, K1_SMEM);

    k0<<<64, 256>>>(Wq, Wk);
    k1<<<dim3(16, Bn), 256, K1_SMEM>>>(aq, mask, Wq, Wk, bq, bk, Wv, bv,
                                       attn_out, ctx_out);
}

// round 7
// speedup vs baseline: 1.1449x; 1.1449x over previous
#include <cuda_runtime.h>
#include <math.h>

#define Bn 32
#define Nn 1024
#define Fn 128
#define Dn 128

// dk = (D^-0.5)/N = 1/(sqrt(128)*1024)
#define DKC 8.6316745750311e-05f

typedef unsigned long long ull;

// ---------------- scratch (device globals) ----------------
__device__ float g_M[Fn * Fn];
__device__ float g_Apart[Bn][4][Fn];
__device__ float g_wcomb[Bn][Fn];
__device__ float g_ccomb[Bn];
__device__ float g_n2part[Bn][4];
__device__ float g_invn[Bn];
__device__ float g_Zpart[Bn][4];
__device__ float g_upart[Bn][4][Fn];
__device__ float g_invZ[Bn];
__device__ int   g_cnt1[Bn], g_cnt2[Bn], g_cnt3[Bn], g_cnt4[Bn];
__device__ int   g_flagW[Bn], g_flagN[Bn], g_flagZ[Bn];
__device__ int   g_cntM, g_flagM, g_cntR;

// ---------------- f32x2 helpers ----------------
__device__ __forceinline__ void ffma2(ull& d, ull a, ull b) {
    asm("fma.rn.f32x2 %0, %1, %2, %0;" : "+l"(d) : "l"(a), "l"(b));
}
__device__ __forceinline__ ull pk2(float lo, float hi) {
    ull r; asm("mov.b64 %0, {%1,%2};" : "=l"(r) : "f"(lo), "f"(hi)); return r;
}
__device__ __forceinline__ void upk2(ull v, float& lo, float& hi) {
    asm("mov.b64 {%0,%1}, %2;" : "=f"(lo), "=f"(hi) : "l"(v));
}
__device__ __forceinline__ void waitflag(int* f, int t) {
    if (t == 0) { while (atomicAdd(f, 0) == 0) __nanosleep(64); }
    __syncthreads();
    __threadfence();
}

// ============ k1: single persistent fused kernel, 128 blocks (one wave) ============
#define STM 129
#define STX 66
#define K1_SMEM ((Fn * STM + Fn * STX) * 4)

__global__ void __launch_bounds__(256, 1) k1(const float* __restrict__ aq,
                                             const float* __restrict__ mask,
                                             const float* __restrict__ Wq,
                                             const float* __restrict__ Wk,
                                             const float* __restrict__ bq,
                                             const float* __restrict__ bk,
                                             const float* __restrict__ Wv,
                                             const float* __restrict__ bv,
                                             float* __restrict__ attn_out,
                                             float* __restrict__ ctx_out) {
    extern __shared__ float sm[];
    float* sM  = sm;                     // [128][129] (dead after main loops)
    float* sXT = sm + Fn * STM;          // [128 f][66] one 64-atom tile
    __shared__ float sWq[128], sA[128], sT[128], sbq[128], sWc[128];
    __shared__ float sMaskAll[256], aggAll[256];
    __shared__ float sStage[1024], sTmp[256], sred[8];
    __shared__ int isL1, isL3;

    const int p = blockIdx.x;            // 0..127
    const int b = p >> 2, j = p & 3;     // batch, quarter
    const int t = threadIdx.x;
    const int warp = t >> 5, lane = t & 31;
    const int r0 = warp * 8;
    const int atomBase = j * 256;

    // ---------- A0: compute M row p ----------
    if (t < 128) sWq[t] = Wq[p * Fn + t];
    __syncthreads();
    {
        int c = t & 127, hh = (t >> 7) * 64;
        const float4* wk4 = reinterpret_cast<const float4*>(Wk + c * Fn + hh);
        const float* sq = sWq + hh;
        float a0 = 0.f, a1 = 0.f, a2 = 0.f, a3 = 0.f;
        #pragma unroll
        for (int q = 0; q < 16; q += 4) {
            float4 v0 = wk4[q], v1 = wk4[q + 1], v2 = wk4[q + 2], v3 = wk4[q + 3];
            a0 = fmaf(sq[4*q + 0], v0.x, a0); a0 = fmaf(sq[4*q + 1], v0.y, a0);
            a0 = fmaf(sq[4*q + 2], v0.z, a0); a0 = fmaf(sq[4*q + 3], v0.w, a0);
            a1 = fmaf(sq[4*q + 4], v1.x, a1); a1 = fmaf(sq[4*q + 5], v1.y, a1);
            a1 = fmaf(sq[4*q + 6], v1.z, a1); a1 = fmaf(sq[4*q + 7], v1.w, a1);
            a2 = fmaf(sq[4*q + 8], v2.x, a2); a2 = fmaf(sq[4*q + 9], v2.y, a2);
            a2 = fmaf(sq[4*q +10], v2.z, a2); a2 = fmaf(sq[4*q +11], v2.w, a2);
            a3 = fmaf(sq[4*q +12], v3.x, a3); a3 = fmaf(sq[4*q +13], v3.y, a3);
            a3 = fmaf(sq[4*q +14], v3.z, a3); a3 = fmaf(sq[4*q +15], v3.w, a3);
        }
        sTmp[t] = (a0 + a1) + (a2 + a3);
    }
    __syncthreads();
    if (t < 128) g_M[p * Fn + t] = sTmp[t] + sTmp[t + 128];
    __threadfence();
    __syncthreads();
    if (t == 0 && atomicAdd(&g_cntM, 1) == 127) atomicExch(&g_flagM, 1);

    // ---------- A1: colsum of my 256 atoms (cold gmem, coalesced float4) ----------
    {
        int fq = (t & 31) * 4, rg = t >> 5;
        const float* pp = aq + ((size_t)(b * Nn + atomBase + rg * 32)) * Fn + fq;
        float4 s0 = {0,0,0,0}, s1 = {0,0,0,0}, s2 = {0,0,0,0}, s3 = {0,0,0,0};
        #pragma unroll
        for (int r = 0; r < 32; r += 4) {
            float4 v0 = *reinterpret_cast<const float4*>(pp + (r + 0) * Fn);
            float4 v1 = *reinterpret_cast<const float4*>(pp + (r + 1) * Fn);
            float4 v2 = *reinterpret_cast<const float4*>(pp + (r + 2) * Fn);
            float4 v3 = *reinterpret_cast<const float4*>(pp + (r + 3) * Fn);
            s0.x += v0.x; s0.y += v0.y; s0.z += v0.z; s0.w += v0.w;
            s1.x += v1.x; s1.y += v1.y; s1.z += v1.z; s1.w += v1.w;
            s2.x += v2.x; s2.y += v2.y; s2.z += v2.z; s2.w += v2.w;
            s3.x += v3.x; s3.y += v3.y; s3.z += v3.z; s3.w += v3.w;
        }
        sStage[rg * 128 + fq + 0] = (s0.x + s1.x) + (s2.x + s3.x);
        sStage[rg * 128 + fq + 1] = (s0.y + s1.y) + (s2.y + s3.y);
        sStage[rg * 128 + fq + 2] = (s0.z + s1.z) + (s2.z + s3.z);
        sStage[rg * 128 + fq + 3] = (s0.w + s1.w) + (s2.w + s3.w);
    }
    sMaskAll[t] = mask[b * Nn + atomBase + t];
    __syncthreads();
    if (t < 128) {
        float s = 0.f;
        #pragma unroll
        for (int g = 0; g < 8; g++) s += sStage[g * 128 + t];
        g_Apart[b][j][t] = s;
    }
    __threadfence();
    __syncthreads();
    if (t == 0) isL1 = (atomicAdd(&g_cnt1[b], 1) == 3);
    __syncthreads();

    // ---------- A2: last block of batch computes wcomb/ccomb ----------
    if (isL1) {
        if (t < 128) {
            float s = 0.f;
            #pragma unroll
            for (int c = 0; c < 4; c++) s += __ldcg(&g_Apart[b][c][t]);
            sA[t] = s;
            sbq[t] = bq[t];
        }
        __syncthreads();
        if (t < 128) {
            float s0 = 0.f, s1 = 0.f, s2 = 0.f, s3 = 0.f;
            #pragma unroll 8
            for (int f = 0; f < Fn; f += 4) {
                s0 = fmaf(Wk[(f + 0) * Fn + t], sA[f + 0], s0);
                s1 = fmaf(Wk[(f + 1) * Fn + t], sA[f + 1], s1);
                s2 = fmaf(Wk[(f + 2) * Fn + t], sA[f + 2], s2);
                s3 = fmaf(Wk[(f + 3) * Fn + t], sA[f + 3], s3);
            }
            sT[t] = (s0 + s1) + (s2 + s3) + 1023.0f * bk[t];  // S - bk
        }
        __syncthreads();
        float cc = 0.f;
        if (t < 128) {
            const float4* wq4 = reinterpret_cast<const float4*>(Wq + t * Fn);
            const float4* wk4 = reinterpret_cast<const float4*>(Wk + t * Fn);
            float w0 = 0.f, w1 = 0.f, w2 = 0.f, w3 = 0.f;
            #pragma unroll 8
            for (int q = 0; q < 32; q += 2) {
                float4 a = wq4[q], b4 = wk4[q], c4 = wq4[q + 1], d4 = wk4[q + 1];
                int d0 = 4 * q, d1 = 4 * q + 4;
                w0 = fmaf(a.x, sT[d0 + 0], w0);  w1 = fmaf(-b4.x, sbq[d0 + 0], w1);
                w0 = fmaf(a.y, sT[d0 + 1], w0);  w1 = fmaf(-b4.y, sbq[d0 + 1], w1);
                w0 = fmaf(a.z, sT[d0 + 2], w0);  w1 = fmaf(-b4.z, sbq[d0 + 2], w1);
                w0 = fmaf(a.w, sT[d0 + 3], w0);  w1 = fmaf(-b4.w, sbq[d0 + 3], w1);
                w2 = fmaf(c4.x, sT[d1 + 0], w2); w3 = fmaf(-d4.x, sbq[d1 + 0], w3);
                w2 = fmaf(c4.y, sT[d1 + 1], w2); w3 = fmaf(-d4.y, sbq[d1 + 1], w3);
                w2 = fmaf(c4.z, sT[d1 + 2], w2); w3 = fmaf(-d4.z, sbq[d1 + 2], w3);
                w2 = fmaf(c4.w, sT[d1 + 3], w2); w3 = fmaf(-d4.w, sbq[d1 + 3], w3);
            }
            g_wcomb[b][t] = (w0 + w1) + (w2 + w3);
            cc = sbq[t] * sT[t];
        }
        #pragma unroll
        for (int off = 16; off > 0; off >>= 1)
            cc += __shfl_xor_sync(0xffffffffu, cc, off);
        if (lane == 0 && warp < 4) sred[warp] = cc;
        __syncthreads();
        if (t == 0) {
            g_ccomb[b] = sred[0] + sred[1] + sred[2] + sred[3];
            __threadfence();
            atomicExch(&g_flagW[b], 1);
        }
    }

    // ---------- load M into SMEM (after global M ready) ----------
    waitflag(&g_flagM, t);
    for (int idx = t; idx < Fn * Fn; idx += 256)
        sM[(idx >> 7) * STM + (idx & 127)] = __ldcg(&g_M[idx]);

    // ---------- Phase C: 4 tiles of 64 atoms; FFMA2 main loop + agg ----------
    float ccomb = 0.f;
    float n2local = 0.f;
    for (int i = 0; i < 4; i++) {
        __syncthreads();   // prev-tile epilogue readers done; also fences sM stores (i=0)
        const float* aqb = aq + ((size_t)(b * Nn + atomBase + i * 64)) * Fn;
        for (int idx = t; idx < 64 * Fn; idx += 256)
            sXT[(idx & 127) * STX + (idx >> 7)] = aqb[idx];
        __syncthreads();

        ull acc[4][4];
        #pragma unroll
        for (int k = 0; k < 4; k++)
            #pragma unroll
            for (int a2 = 0; a2 < 4; a2++) acc[k][a2] = 0ull;

        #pragma unroll 4
        for (int g = 0; g < Fn; g++) {
            const float* xp = &sXT[g * STX + r0];
            ull x0 = *reinterpret_cast<const ull*>(xp + 0);
            ull x1 = *reinterpret_cast<const ull*>(xp + 2);
            ull x2 = *reinterpret_cast<const ull*>(xp + 4);
            ull x3 = *reinterpret_cast<const ull*>(xp + 6);
            #pragma unroll
            for (int k = 0; k < 4; k++) {
                float m = sM[(lane + 32 * k) * STM + g];
                ull mm = pk2(m, m);
                ffma2(acc[k][0], mm, x0);
                ffma2(acc[k][1], mm, x1);
                ffma2(acc[k][2], mm, x2);
                ffma2(acc[k][3], mm, x3);
            }
        }

        if (i == 0) {   // first tile: fetch wcomb/ccomb (flag almost surely set by now)
            waitflag(&g_flagW[b], t);
            if (t < 128) sWc[t] = __ldcg(&g_wcomb[b][t]);
            __syncthreads();
            ccomb = __ldcg(&g_ccomb[b]);
        }

        float wc[4];
        #pragma unroll
        for (int k = 0; k < 4; k++) wc[k] = sWc[lane + 32 * k];

        #pragma unroll
        for (int a2 = 0; a2 < 4; a2++) {
            float ylo[4], yhi[4];
            #pragma unroll
            for (int k = 0; k < 4; k++) upk2(acc[k][a2], ylo[k], yhi[k]);
            #pragma unroll
            for (int half = 0; half < 2; half++) {
                int a = 2 * a2 + half;
                float p1 = 0.f, p2 = 0.f;
                #pragma unroll
                for (int k = 0; k < 4; k++) {
                    float xf = sXT[(lane + 32 * k) * STX + r0 + a];
                    p1 = fmaf(xf, half ? yhi[k] : ylo[k], p1);
                    p2 = fmaf(xf, wc[k], p2);
                }
                #pragma unroll
                for (int off = 16; off > 0; off >>= 1) {
                    p1 += __shfl_xor_sync(0xffffffffu, p1, off);
                    p2 += __shfl_xor_sync(0xffffffffu, p2, off);
                }
                if (lane == 0) {
                    float mv = sMaskAll[i * 64 + r0 + a];
                    float aggv = mv * DKC * (p2 + ccomb - p1);
                    aggAll[i * 64 + r0 + a] = aggv;
                    n2local = fmaf(aggv, aggv, n2local);
                }
            }
        }
    }
    if (lane == 0) sred[warp] = n2local;
    __syncthreads();
    if (t == 0) {
        float s = 0.f;
        #pragma unroll
        for (int w = 0; w < 8; w++) s += sred[w];
        g_n2part[b][j] = s;
        __threadfence();
        if (atomicAdd(&g_cnt2[b], 1) == 3) {
            float n2 = 0.f;
            #pragma unroll
            for (int c = 0; c < 4; c++) n2 += __ldcg(&g_n2part[b][c]);
            g_invn[b] = rsqrtf(n2);
            __threadfence();
            atomicExch(&g_flagN[b], 1);
        }
    }

    // ---------- Phase D: exp, Z partial, weighted colsum (aq L2-hot reload) ----------
    waitflag(&g_flagN[b], t);
    const float invn = __ldcg(&g_invn[b]);
    float e = (sMaskAll[t] != 0.f) ? __expf(aggAll[t] * invn) : 0.f;
    __syncthreads();        // aggAll readers (none) / ensure agg phase done
    aggAll[t] = e;          // now holds e values
    float ze = e;
    #pragma unroll
    for (int off = 16; off > 0; off >>= 1) ze += __shfl_xor_sync(0xffffffffu, ze, off);
    if (lane == 0) sred[warp] = ze;
    __syncthreads();

    {
        int f = t & 127, h = (t >> 7) * 32;
        float ua0 = 0.f, ua1 = 0.f, ua2 = 0.f, ua3 = 0.f;
        for (int i = 0; i < 4; i++) {
            __syncthreads();
            const float* aqb = aq + ((size_t)(b * Nn + atomBase + i * 64)) * Fn;
            for (int idx = t; idx < 64 * Fn; idx += 256)
                sXT[(idx & 127) * STX + (idx >> 7)] = aqb[idx];
            __syncthreads();
            const float* ep = &aggAll[i * 64 + h];
            const float* xp = &sXT[f * STX + h];
            #pragma unroll
            for (int a = 0; a < 32; a += 4) {
                ua0 = fmaf(ep[a + 0], xp[a + 0], ua0);
                ua1 = fmaf(ep[a + 1], xp[a + 1], ua1);
                ua2 = fmaf(ep[a + 2], xp[a + 2], ua2);
                ua3 = fmaf(ep[a + 3], xp[a + 3], ua3);
            }
        }
        sTmp[t] = (ua0 + ua1) + (ua2 + ua3);
    }
    __syncthreads();
    if (t < 128) g_upart[b][j][t] = sTmp[t] + sTmp[t + 128];
    if (t == 0) {
        float z = 0.f;
        #pragma unroll
        for (int w = 0; w < 8; w++) z += sred[w];
        g_Zpart[b][j] = z;
    }
    __threadfence();
    __syncthreads();
    if (t == 0) {
        isL3 = (atomicAdd(&g_cnt3[b], 1) == 3);
        if (isL3) {
            float Z = 0.f;
            #pragma unroll
            for (int c = 0; c < 4; c++) Z += __ldcg(&g_Zpart[b][c]);
            g_invZ[b] = 1.0f / Z;
            __threadfence();
            atomicExch(&g_flagZ[b], 1);
        }
    }
    __syncthreads();

    // ---------- Phase E: attn out; last block computes context ----------
    waitflag(&g_flagZ[b], t);
    const float invZ = __ldcg(&g_invZ[b]);
    if (attn_out) attn_out[b * Nn + atomBase + t] = aggAll[t] * invZ;
    __syncthreads();

    if (isL3) {
        float* sU = sTmp;       // [0..127] reduced u vector
        float* spart = sm;      // extern SMEM region is dead here
        if (t < 128) {
            float s = 0.f;
            #pragma unroll
            for (int c = 0; c < 4; c++) s += __ldcg(&g_upart[b][c][t]);
            sU[t] = s;
        }
        __syncthreads();
        if (ctx_out) {
            int g = t >> 7, d = t & 127;
            int f0 = g * 64;
            float c0 = 0.f, c1 = 0.f, c2 = 0.f, c3 = 0.f;
            #pragma unroll 4
            for (int f = f0; f < f0 + 64; f += 4) {
                c0 = fmaf(Wv[(f + 0) * Fn + d], sU[f + 0], c0);
                c1 = fmaf(Wv[(f + 1) * Fn + d], sU[f + 1], c1);
                c2 = fmaf(Wv[(f + 2) * Fn + d], sU[f + 2], c2);
                c3 = fmaf(Wv[(f + 3) * Fn + d], sU[f + 3], c3);
            }
            spart[t] = (c0 + c1) + (c2 + c3);
            __syncthreads();
            if (t < 128)
                ctx_out[b * Dn + t] = (spart[t] + spart[t + 128]) * invZ + bv[t];
        }
    }

    // ---------- reset for graph replay ----------
    __threadfence();
    __syncthreads();
    if (t == 0) {
        if (atomicAdd(&g_cnt4[b], 1) == 3) {
            g_cnt1[b] = 0; g_cnt2[b] = 0; g_cnt3[b] = 0; g_cnt4[b] = 0;
            g_flagW[b] = 0; g_flagN[b] = 0; g_flagZ[b] = 0;
            if (atomicAdd(&g_cntR, 1) == 31) {
                g_cntM = 0; g_flagM = 0; g_cntR = 0;
            }
        }
    }
}

// ---------------- host launch ----------------
extern "C" void kernel_launch(void* const* d_in, const int* in_sizes, int n_in,
                              void* d_out, int out_size) {
    const float* aq   = (const float*)d_in[0];
    const float* mask = (const float*)d_in[1];
    const float* Wq   = (const float*)d_in[2];
    const float* bq   = (const float*)d_in[3];
    const float* Wk   = (const float*)d_in[4];
    const float* bk   = (const float*)d_in[5];
    const float* Wv   = (const float*)d_in[6];
    const float* bv   = (const float*)d_in[7];

    float* out = (float*)d_out;
    float* attn_out = nullptr;
    float* ctx_out = nullptr;
    if (out_size >= Bn * Nn + Bn * Dn) { attn_out = out; ctx_out = out + Bn * Nn; }
    else if (out_size == Bn * Nn)      { attn_out = out; }
    else                               { ctx_out = out; }

    cudaFuncSetAttribute(k1, cudaFuncAttributeMaxDynamicSharedMemorySize, K1_SMEM);

    k1<<<128, 256, K1_SMEM>>>(aq, mask, Wq, Wk, bq, bk, Wv, bv,
                              attn_out, ctx_out);
}

// round 8
// speedup vs baseline: 1.3224x; 1.1551x over previous
#include <cuda_runtime.h>
#include <math.h>

#define Bn 32
#define Nn 1024
#define Fn 128
#define Dn 128

// dk = (D^-0.5)/N = 1/(sqrt(128)*1024)
#define DKC 8.6316745750311e-05f

// ---------------- scratch (device globals) ----------------
__device__ float g_M[Fn * Fn];
__device__ float g_Apart[Bn][4][Fn];
__device__ float g_wcomb[Bn][Fn];
__device__ float g_ccomb[Bn];
__device__ float g_n2part[Bn][4];
__device__ float g_invn[Bn];
__device__ float g_Zpart[Bn][4];
__device__ float g_upart[Bn][4][Fn];
__device__ float g_invZ[Bn];
__device__ int   g_cnt1[Bn], g_cnt2[Bn], g_cnt3[Bn], g_cnt4[Bn];
__device__ int   g_flagW[Bn], g_flagN[Bn], g_flagZ[Bn];
__device__ int   g_cntM, g_flagM, g_cntR;

// ---------------- helpers ----------------
__device__ __forceinline__ unsigned f2tf(float f) {
    unsigned r; asm("cvt.rna.tf32.f32 %0, %1;" : "=r"(r) : "f"(f)); return r;
}
__device__ __forceinline__ void mma_tf32(float c[4], unsigned a0, unsigned a1,
                                         unsigned a2, unsigned a3,
                                         unsigned b0, unsigned b1) {
    asm("mma.sync.aligned.m16n8k8.row.col.f32.tf32.tf32.f32 "
        "{%0,%1,%2,%3}, {%4,%5,%6,%7}, {%8,%9}, {%0,%1,%2,%3};"
        : "+f"(c[0]), "+f"(c[1]), "+f"(c[2]), "+f"(c[3])
        : "r"(a0), "r"(a1), "r"(a2), "r"(a3), "r"(b0), "r"(b1));
}
__device__ __forceinline__ void waitflag(int* f, int t) {
    if (t == 0) { while (atomicAdd(f, 0) == 0) __nanosleep(64); }
    __syncthreads();
    __threadfence();
}

// ============ k1: single persistent fused kernel, 128 blocks (one wave) ============
#define STM 129      // M (tf32) row stride
#define STX 66       // fp32 X[f][atom] stride
#define STXF 72      // tf32 X[g][atom] stride (conflict-free B-frag loads)
#define STY 66       // Y[f][atom] stride
#define K1_SMEM ((Fn * STM + Fn * STX + Fn * STXF + Fn * STY) * 4)

__global__ void __launch_bounds__(256, 1) k1(const float* __restrict__ aq,
                                             const float* __restrict__ mask,
                                             const float* __restrict__ Wq,
                                             const float* __restrict__ Wk,
                                             const float* __restrict__ bq,
                                             const float* __restrict__ bk,
                                             const float* __restrict__ Wv,
                                             const float* __restrict__ bv,
                                             float* __restrict__ attn_out,
                                             float* __restrict__ ctx_out) {
    extern __shared__ float sm[];
    unsigned* sMu   = (unsigned*)sm;                 // [128][129] tf32 M
    float*    sXT   = sm + Fn * STM;                 // [128 f][66] fp32 tile
    unsigned* sXtfu = (unsigned*)(sXT + Fn * STX);   // [128 g][72] tf32 tile
    float*    sY    = sXT + Fn * STX + Fn * STXF;    // [128 f][66] Y = M X
    __shared__ float sWq[128], sA[128], sT[128], sbq[128], sWc[128];
    __shared__ float sMaskAll[256], aggAll[256];
    __shared__ float sStage[1024], sTmp[256], sred[8];
    __shared__ int isL1, isL3;

    const int p = blockIdx.x;            // 0..127
    const int b = p >> 2, j = p & 3;     // batch, quarter
    const int t = threadIdx.x;
    const int warp = t >> 5, lane = t & 31;
    const int r0 = warp * 8;
    const int gid = lane >> 2, tid4 = lane & 3;
    const int atomBase = j * 256;

    // ---------- A0: compute M row p ----------
    if (t < 128) sWq[t] = Wq[p * Fn + t];
    __syncthreads();
    {
        int c = t & 127, hh = (t >> 7) * 64;
        const float4* wk4 = reinterpret_cast<const float4*>(Wk + c * Fn + hh);
        const float* sq = sWq + hh;
        float a0 = 0.f, a1 = 0.f, a2 = 0.f, a3 = 0.f;
        #pragma unroll
        for (int q = 0; q < 16; q += 4) {
            float4 v0 = wk4[q], v1 = wk4[q + 1], v2 = wk4[q + 2], v3 = wk4[q + 3];
            a0 = fmaf(sq[4*q + 0], v0.x, a0); a0 = fmaf(sq[4*q + 1], v0.y, a0);
            a0 = fmaf(sq[4*q + 2], v0.z, a0); a0 = fmaf(sq[4*q + 3], v0.w, a0);
            a1 = fmaf(sq[4*q + 4], v1.x, a1); a1 = fmaf(sq[4*q + 5], v1.y, a1);
            a1 = fmaf(sq[4*q + 6], v1.z, a1); a1 = fmaf(sq[4*q + 7], v1.w, a1);
            a2 = fmaf(sq[4*q + 8], v2.x, a2); a2 = fmaf(sq[4*q + 9], v2.y, a2);
            a2 = fmaf(sq[4*q +10], v2.z, a2); a2 = fmaf(sq[4*q +11], v2.w, a2);
            a3 = fmaf(sq[4*q +12], v3.x, a3); a3 = fmaf(sq[4*q +13], v3.y, a3);
            a3 = fmaf(sq[4*q +14], v3.z, a3); a3 = fmaf(sq[4*q +15], v3.w, a3);
        }
        sTmp[t] = (a0 + a1) + (a2 + a3);
    }
    __syncthreads();
    if (t < 128) g_M[p * Fn + t] = sTmp[t] + sTmp[t + 128];
    __threadfence();
    __syncthreads();
    if (t == 0 && atomicAdd(&g_cntM, 1) == 127) atomicExch(&g_flagM, 1);

    // ---------- A1: colsum of my 256 atoms (cold gmem, coalesced float4) ----------
    {
        int fq = (t & 31) * 4, rg = t >> 5;
        const float* pp = aq + ((size_t)(b * Nn + atomBase + rg * 32)) * Fn + fq;
        float4 s0 = {0,0,0,0}, s1 = {0,0,0,0}, s2 = {0,0,0,0}, s3 = {0,0,0,0};
        #pragma unroll
        for (int r = 0; r < 32; r += 4) {
            float4 v0 = *reinterpret_cast<const float4*>(pp + (r + 0) * Fn);
            float4 v1 = *reinterpret_cast<const float4*>(pp + (r + 1) * Fn);
            float4 v2 = *reinterpret_cast<const float4*>(pp + (r + 2) * Fn);
            float4 v3 = *reinterpret_cast<const float4*>(pp + (r + 3) * Fn);
            s0.x += v0.x; s0.y += v0.y; s0.z += v0.z; s0.w += v0.w;
            s1.x += v1.x; s1.y += v1.y; s1.z += v1.z; s1.w += v1.w;
            s2.x += v2.x; s2.y += v2.y; s2.z += v2.z; s2.w += v2.w;
            s3.x += v3.x; s3.y += v3.y; s3.z += v3.z; s3.w += v3.w;
        }
        sStage[rg * 128 + fq + 0] = (s0.x + s1.x) + (s2.x + s3.x);
        sStage[rg * 128 + fq + 1] = (s0.y + s1.y) + (s2.y + s3.y);
        sStage[rg * 128 + fq + 2] = (s0.z + s1.z) + (s2.z + s3.z);
        sStage[rg * 128 + fq + 3] = (s0.w + s1.w) + (s2.w + s3.w);
    }
    sMaskAll[t] = mask[b * Nn + atomBase + t];
    __syncthreads();
    if (t < 128) {
        float s = 0.f;
        #pragma unroll
        for (int g = 0; g < 8; g++) s += sStage[g * 128 + t];
        g_Apart[b][j][t] = s;
    }
    __threadfence();
    __syncthreads();
    if (t == 0) isL1 = (atomicAdd(&g_cnt1[b], 1) == 3);
    __syncthreads();

    // ---------- A2: last block of batch computes wcomb/ccomb ----------
    if (isL1) {
        if (t < 128) {
            float s = 0.f;
            #pragma unroll
            for (int c = 0; c < 4; c++) s += __ldcg(&g_Apart[b][c][t]);
            sA[t] = s;
            sbq[t] = bq[t];
        }
        __syncthreads();
        if (t < 128) {
            float s0 = 0.f, s1 = 0.f, s2 = 0.f, s3 = 0.f;
            #pragma unroll 8
            for (int f = 0; f < Fn; f += 4) {
                s0 = fmaf(Wk[(f + 0) * Fn + t], sA[f + 0], s0);
                s1 = fmaf(Wk[(f + 1) * Fn + t], sA[f + 1], s1);
                s2 = fmaf(Wk[(f + 2) * Fn + t], sA[f + 2], s2);
                s3 = fmaf(Wk[(f + 3) * Fn + t], sA[f + 3], s3);
            }
            sT[t] = (s0 + s1) + (s2 + s3) + 1023.0f * bk[t];  // S - bk
        }
        __syncthreads();
        float cc = 0.f;
        if (t < 128) {
            const float4* wq4 = reinterpret_cast<const float4*>(Wq + t * Fn);
            const float4* wk4 = reinterpret_cast<const float4*>(Wk + t * Fn);
            float w0 = 0.f, w1 = 0.f, w2 = 0.f, w3 = 0.f;
            #pragma unroll 8
            for (int q = 0; q < 32; q += 2) {
                float4 a = wq4[q], b4 = wk4[q], c4 = wq4[q + 1], d4 = wk4[q + 1];
                int d0 = 4 * q, d1 = 4 * q + 4;
                w0 = fmaf(a.x, sT[d0 + 0], w0);  w1 = fmaf(-b4.x, sbq[d0 + 0], w1);
                w0 = fmaf(a.y, sT[d0 + 1], w0);  w1 = fmaf(-b4.y, sbq[d0 + 1], w1);
                w0 = fmaf(a.z, sT[d0 + 2], w0);  w1 = fmaf(-b4.z, sbq[d0 + 2], w1);
                w0 = fmaf(a.w, sT[d0 + 3], w0);  w1 = fmaf(-b4.w, sbq[d0 + 3], w1);
                w2 = fmaf(c4.x, sT[d1 + 0], w2); w3 = fmaf(-d4.x, sbq[d1 + 0], w3);
                w2 = fmaf(c4.y, sT[d1 + 1], w2); w3 = fmaf(-d4.y, sbq[d1 + 1], w3);
                w2 = fmaf(c4.z, sT[d1 + 2], w2); w3 = fmaf(-d4.z, sbq[d1 + 2], w3);
                w2 = fmaf(c4.w, sT[d1 + 3], w2); w3 = fmaf(-d4.w, sbq[d1 + 3], w3);
            }
            g_wcomb[b][t] = (w0 + w1) + (w2 + w3);
            cc = sbq[t] * sT[t];
        }
        #pragma unroll
        for (int off = 16; off > 0; off >>= 1)
            cc += __shfl_xor_sync(0xffffffffu, cc, off);
        if (lane == 0 && warp < 4) sred[warp] = cc;
        __syncthreads();
        if (t == 0) {
            g_ccomb[b] = sred[0] + sred[1] + sred[2] + sred[3];
            __threadfence();
            atomicExch(&g_flagW[b], 1);
        }
    }

    // ---------- load M into SMEM as tf32 (after global M ready) ----------
    waitflag(&g_flagM, t);
    for (int idx = t; idx < Fn * Fn; idx += 256)
        sMu[(idx >> 7) * STM + (idx & 127)] = f2tf(__ldcg(&g_M[idx]));

    // ---------- Phase C: 4 tiles of 64 atoms; tf32 MMA + agg ----------
    float ccomb = 0.f;
    float n2local = 0.f;
    const int mb = warp * 16;
    for (int i = 0; i < 4; i++) {
        __syncthreads();   // prev-tile readers done; fences sM stores (i=0)
        const float* aqb = aq + ((size_t)(b * Nn + atomBase + i * 64)) * Fn;
        for (int idx = t; idx < 64 * Fn; idx += 256) {
            float v = aqb[idx];
            int f = idx & 127, a = idx >> 7;
            sXT[f * STX + a] = v;
            sXtfu[f * STXF + a] = f2tf(v);
        }
        __syncthreads();

        // Y[128 x 64] = M x X via m16n8k8 tf32; warp owns 16 f-rows, all 64 cols
        float yc[8][4];
        #pragma unroll
        for (int nb = 0; nb < 8; nb++)
            #pragma unroll
            for (int q = 0; q < 4; q++) yc[nb][q] = 0.f;

        #pragma unroll
        for (int kb = 0; kb < 16; kb++) {
            int k0 = kb * 8;
            unsigned a0 = sMu[(mb + gid) * STM + k0 + tid4];
            unsigned a1 = sMu[(mb + gid + 8) * STM + k0 + tid4];
            unsigned a2 = sMu[(mb + gid) * STM + k0 + tid4 + 4];
            unsigned a3 = sMu[(mb + gid + 8) * STM + k0 + tid4 + 4];
            #pragma unroll
            for (int nb = 0; nb < 8; nb++) {
                unsigned b0 = sXtfu[(k0 + tid4) * STXF + nb * 8 + gid];
                unsigned b1 = sXtfu[(k0 + tid4 + 4) * STXF + nb * 8 + gid];
                mma_tf32(yc[nb], a0, a1, a2, a3, b0, b1);
            }
        }
        #pragma unroll
        for (int nb = 0; nb < 8; nb++) {
            int col = nb * 8 + 2 * tid4;
            *reinterpret_cast<float2*>(&sY[(mb + gid) * STY + col]) =
                make_float2(yc[nb][0], yc[nb][1]);
            *reinterpret_cast<float2*>(&sY[(mb + gid + 8) * STY + col]) =
                make_float2(yc[nb][2], yc[nb][3]);
        }

        if (i == 0) {   // fetch wcomb/ccomb (flag long set — A2 overlapped)
            waitflag(&g_flagW[b], t);
            if (t < 128) sWc[t] = __ldcg(&g_wcomb[b][t]);
            __syncthreads();
            ccomb = __ldcg(&g_ccomb[b]);
        }
        __syncthreads();   // sY ready

        float wc[4];
        #pragma unroll
        for (int k = 0; k < 4; k++) wc[k] = sWc[lane + 32 * k];

        #pragma unroll
        for (int a = 0; a < 8; a++) {
            float p1 = 0.f, p2 = 0.f;
            #pragma unroll
            for (int k = 0; k < 4; k++) {
                int f = lane + 32 * k;
                float xf = sXT[f * STX + r0 + a];
                float yf = sY[f * STY + r0 + a];
                p1 = fmaf(xf, yf, p1);
                p2 = fmaf(xf, wc[k], p2);
            }
            #pragma unroll
            for (int off = 16; off > 0; off >>= 1) {
                p1 += __shfl_xor_sync(0xffffffffu, p1, off);
                p2 += __shfl_xor_sync(0xffffffffu, p2, off);
            }
            if (lane == 0) {
                float mv = sMaskAll[i * 64 + r0 + a];
                float aggv = mv * DKC * (p2 + ccomb - p1);
                aggAll[i * 64 + r0 + a] = aggv;
                n2local = fmaf(aggv, aggv, n2local);
            }
        }
    }
    if (lane == 0) sred[warp] = n2local;
    __syncthreads();
    if (t == 0) {
        float s = 0.f;
        #pragma unroll
        for (int w = 0; w < 8; w++) s += sred[w];
        g_n2part[b][j] = s;
        __threadfence();
        if (atomicAdd(&g_cnt2[b], 1) == 3) {
            float n2 = 0.f;
            #pragma unroll
            for (int c = 0; c < 4; c++) n2 += __ldcg(&g_n2part[b][c]);
            g_invn[b] = rsqrtf(n2);
            __threadfence();
            atomicExch(&g_flagN[b], 1);
        }
    }

    // ---------- Phase D: exp, Z partial, weighted colsum (aq L2-hot reload) ----------
    waitflag(&g_flagN[b], t);
    const float invn = __ldcg(&g_invn[b]);
    float e = (sMaskAll[t] != 0.f) ? __expf(aggAll[t] * invn) : 0.f;
    __syncthreads();
    aggAll[t] = e;          // now holds e values
    float ze = e;
    #pragma unroll
    for (int off = 16; off > 0; off >>= 1) ze += __shfl_xor_sync(0xffffffffu, ze, off);
    if (lane == 0) sred[warp] = ze;
    __syncthreads();

    {
        int f = t & 127, h = (t >> 7) * 32;
        float ua0 = 0.f, ua1 = 0.f, ua2 = 0.f, ua3 = 0.f;
        for (int i = 0; i < 4; i++) {
            __syncthreads();
            const float* aqb = aq + ((size_t)(b * Nn + atomBase + i * 64)) * Fn;
            for (int idx = t; idx < 64 * Fn; idx += 256)
                sXT[(idx & 127) * STX + (idx >> 7)] = aqb[idx];
            __syncthreads();
            const float* ep = &aggAll[i * 64 + h];
            const float* xp = &sXT[f * STX + h];
            #pragma unroll
            for (int a = 0; a < 32; a += 4) {
                ua0 = fmaf(ep[a + 0], xp[a + 0], ua0);
                ua1 = fmaf(ep[a + 1], xp[a + 1], ua1);
                ua2 = fmaf(ep[a + 2], xp[a + 2], ua2);
                ua3 = fmaf(ep[a + 3], xp[a + 3], ua3);
            }
        }
        sTmp[t] = (ua0 + ua1) + (ua2 + ua3);
    }
    __syncthreads();
    if (t < 128) g_upart[b][j][t] = sTmp[t] + sTmp[t + 128];
    if (t == 0) {
        float z = 0.f;
        #pragma unroll
        for (int w = 0; w < 8; w++) z += sred[w];
        g_Zpart[b][j] = z;
    }
    __threadfence();
    __syncthreads();
    if (t == 0) {
        isL3 = (atomicAdd(&g_cnt3[b], 1) == 3);
        if (isL3) {
            float Z = 0.f;
            #pragma unroll
            for (int c = 0; c < 4; c++) Z += __ldcg(&g_Zpart[b][c]);
            g_invZ[b] = 1.0f / Z;
            __threadfence();
            atomicExch(&g_flagZ[b], 1);
        }
    }
    __syncthreads();

    // ---------- Phase E: attn out; last block computes context ----------
    waitflag(&g_flagZ[b], t);
    const float invZ = __ldcg(&g_invZ[b]);
    if (attn_out) attn_out[b * Nn + atomBase + t] = aggAll[t] * invZ;
    __syncthreads();

    if (isL3) {
        float* sU = sTmp;       // [0..127] reduced u vector
        float* spart = sm;      // extern SMEM region is dead here
        if (t < 128) {
            float s = 0.f;
            #pragma unroll
            for (int c = 0; c < 4; c++) s += __ldcg(&g_upart[b][c][t]);
            sU[t] = s;
        }
        __syncthreads();
        if (ctx_out) {
            int g = t >> 7, d = t & 127;
            int f0 = g * 64;
            float c0 = 0.f, c1 = 0.f, c2 = 0.f, c3 = 0.f;
            #pragma unroll 4
            for (int f = f0; f < f0 + 64; f += 4) {
                c0 = fmaf(Wv[(f + 0) * Fn + d], sU[f + 0], c0);
                c1 = fmaf(Wv[(f + 1) * Fn + d], sU[f + 1], c1);
                c2 = fmaf(Wv[(f + 2) * Fn + d], sU[f + 2], c2);
                c3 = fmaf(Wv[(f + 3) * Fn + d], sU[f + 3], c3);
            }
            spart[t] = (c0 + c1) + (c2 + c3);
            __syncthreads();
            if (t < 128)
                ctx_out[b * Dn + t] = (spart[t] + spart[t + 128]) * invZ + bv[t];
        }
    }

    // ---------- reset for graph replay ----------
    __threadfence();
    __syncthreads();
    if (t == 0) {
        if (atomicAdd(&g_cnt4[b], 1) == 3) {
            g_cnt1[b] = 0; g_cnt2[b] = 0; g_cnt3[b] = 0; g_cnt4[b] = 0;
            g_flagW[b] = 0; g_flagN[b] = 0; g_flagZ[b] = 0;
            if (atomicAdd(&g_cntR, 1) == 31) {
                g_cntM = 0; g_flagM = 0; g_cntR = 0;
            }
        }
    }
}

// ---------------- host launch ----------------
extern "C" void kernel_launch(void* const* d_in, const int* in_sizes, int n_in,
                              void* d_out, int out_size) {
    const float* aq   = (const float*)d_in[0];
    const float* mask = (const float*)d_in[1];
    const float* Wq   = (const float*)d_in[2];
    const float* bq   = (const float*)d_in[3];
    const float* Wk   = (const float*)d_in[4];
    const float* bk   = (const float*)d_in[5];
    const float* Wv   = (const float*)d_in[6];
    const float* bv   = (const float*)d_in[7];

    float* out = (float*)d_out;
    float* attn_out = nullptr;
    float* ctx_out = nullptr;
    if (out_size >= Bn * Nn + Bn * Dn) { attn_out = out; ctx_out = out + Bn * Nn; }
    else if (out_size == Bn * Nn)      { attn_out = out; }
    else                               { ctx_out = out; }

    cudaFuncSetAttribute(k1, cudaFuncAttributeMaxDynamicSharedMemorySize, K1_SMEM);

    k1<<<128, 256, K1_SMEM>>>(aq, mask, Wq, Wk, bq, bk, Wv, bv,
                              attn_out, ctx_out);
}